// round 6
// baseline (speedup 1.0000x reference)
#include <cuda_runtime.h>
#include <math.h>

// Problem constants
#define N1v 4000
#define N2v 4000
#define GD  8000
#define RD  20000
#define M1v 1200
#define M2v 1200
#define MGv 2400
#define MRv 6000

#define NBLK 912     // loss kernel blocks (~6/SM resident; dynamic ticketing balances)

// ---------------- device scratch (no allocation allowed) ----------------
__device__ int    d_s1[M1v], d_s2[M2v], d_sg[MGv], d_sr[MRv];
__device__ float  d_w1[M1v], d_w2[M2v], d_wg[MGv], d_wr[MRv];
__device__ float4 d_q1[M1v], d_q2[M2v], d_pg[MGv], d_pr[MRv];
__device__ int    d_nu[4];      // unique counts: [m1, m2, mg, mr]
// 0: loss1 sum, 1: loss2 sum, 2: S (unnormalized trace), 3: ||Pg||^2, 4: ||Pr||^2
__device__ double d_acc[5];
__device__ int    d_ticket, d_done;

// ---------------- helpers ----------------
__device__ __forceinline__ void softmax3(float a, float b, float c,
                                         float& p0, float& p1, float& p2) {
    float m  = fmaxf(a, fmaxf(b, c));
    float e0 = __expf(a - m), e1 = __expf(b - m), e2 = __expf(c - m);
    float inv = 1.0f / (e0 + e1 + e2);
    p0 = e0 * inv; p1 = e1 * inv; p2 = e2 * inv;
}

__device__ __forceinline__ float warp_sum(float v) {
    #pragma unroll
    for (int off = 16; off > 0; off >>= 1)
        v += __shfl_down_sync(0xFFFFFFFFu, v, off);
    return v;
}

// ---------------- fused counting sort + dedup + prep (4 concurrent blocks) ------
// Sorting/dedup is exact: all sums are permutation-invariant and every per-index
// quantity depends only on the mask VALUE; duplicates contribute identical terms,
// captured by multiplicity weights. After its own sort completes, each block
// immediately builds the softmax/Q tables for its axis (purely local dependency).
__global__ void sort_prep_kernel(
        const int* __restrict__ m1, const int* __restrict__ m2,
        const int* __restrict__ mg, const int* __restrict__ mr,
        const float* __restrict__ C1, const float* __restrict__ C2,
        const float* __restrict__ Cg, const float* __restrict__ Cr,
        const float* __restrict__ Ai, const float* __restrict__ bg,
        const float* __restrict__ br, const float* __restrict__ b1,
        const float* __restrict__ b2) {
    extern __shared__ int sh[];           // histogram (up to RD ints)
    __shared__ int wsum[32];
    __shared__ float fpart[32];
    __shared__ int s_nu;
    const int which = blockIdx.x;
    const int tid = threadIdx.x, bd = blockDim.x;   // bd == 1024
    const int lane = tid & 31, wid = tid >> 5;

    const int* in; int n, vmax; int* outv; float* outw;
    if      (which == 0) { in = m1; n = M1v; vmax = N1v; outv = d_s1; outw = d_w1; }
    else if (which == 1) { in = m2; n = M2v; vmax = N2v; outv = d_s2; outw = d_w2; }
    else if (which == 2) { in = mg; n = MGv; vmax = GD;  outv = d_sg; outw = d_wg; }
    else                 { in = mr; n = MRv; vmax = RD;  outv = d_sr; outw = d_wr; }

    if (which == 0) {     // reset global state for this launch (graph replays)
        if (tid < 3) d_acc[tid] = 0.0;
        else if (tid == 3) d_ticket = 0;
        else if (tid == 4) d_done = 0;
    }

    // ---- counting sort ----
    for (int v = tid; v < vmax; v += bd) sh[v] = 0;
    __syncthreads();
    for (int k = tid; k < n; k += bd) atomicAdd(&sh[in[k]], 1);
    __syncthreads();

    const int chunk = (vmax + bd - 1) / bd;
    const int c0 = min(tid * chunk, vmax);
    const int c1 = min(c0 + chunk, vmax);
    int cnt = 0;
    for (int v = c0; v < c1; v++) cnt += (sh[v] != 0);

    // exclusive scan of unique-counts across 1024 threads
    int incl = cnt;
    #pragma unroll
    for (int off = 1; off < 32; off <<= 1) {
        int t = __shfl_up_sync(0xFFFFFFFFu, incl, off);
        if (lane >= off) incl += t;
    }
    if (lane == 31) wsum[wid] = incl;
    __syncthreads();
    if (wid == 0) {
        int s = wsum[lane];
        #pragma unroll
        for (int off = 1; off < 32; off <<= 1) {
            int t = __shfl_up_sync(0xFFFFFFFFu, s, off);
            if (lane >= off) s += t;
        }
        wsum[lane] = s;
    }
    __syncthreads();
    int excl = incl - cnt + (wid > 0 ? wsum[wid - 1] : 0);

    for (int v = c0; v < c1; v++) {
        int c = sh[v];
        if (c) { outv[excl] = v; outw[excl] = (float)c; excl++; }
    }
    if (tid == bd - 1) { d_nu[which] = excl; s_nu = excl; }
    __syncthreads();
    const int nu = s_nu;

    // ---- prep for this axis ----
    float norm2 = 0.0f;
    if (which == 0) {
        float a00=Ai[0],a01=Ai[1],a02=Ai[2],a10=Ai[3],a11=Ai[4],a12=Ai[5],
              a20=Ai[6],a21=Ai[7],a22=Ai[8];
        for (int i = tid; i < nu; i += bd) {
            int v = d_s1[i];
            float p0,p1,p2; softmax3(C1[3*v], C1[3*v+1], C1[3*v+2], p0,p1,p2);
            d_q1[i] = make_float4(p0*a00+p1*a10+p2*a20, p0*a01+p1*a11+p2*a21,
                                  p0*a02+p1*a12+p2*a22, b1[v]);
        }
        return;
    } else if (which == 1) {
        float a00=Ai[0],a01=Ai[1],a02=Ai[2],a10=Ai[3],a11=Ai[4],a12=Ai[5],
              a20=Ai[6],a21=Ai[7],a22=Ai[8];
        for (int i = tid; i < nu; i += bd) {
            int v = d_s2[i];
            float p0,p1,p2; softmax3(C2[3*v], C2[3*v+1], C2[3*v+2], p0,p1,p2);
            d_q2[i] = make_float4(p0*a00+p1*a10+p2*a20, p0*a01+p1*a11+p2*a21,
                                  p0*a02+p1*a12+p2*a22, b2[v]);
        }
        return;
    } else if (which == 2) {
        for (int i = tid; i < nu; i += bd) {
            int v = d_sg[i];
            float p0,p1,p2; softmax3(Cg[3*v], Cg[3*v+1], Cg[3*v+2], p0,p1,p2);
            d_pg[i] = make_float4(p0, p1, p2, bg[v]);
            norm2 += d_wg[i] * (p0*p0 + p1*p1 + p2*p2);
        }
    } else {
        for (int i = tid; i < nu; i += bd) {
            int v = d_sr[i];
            float p0,p1,p2; softmax3(Cr[3*v], Cr[3*v+1], Cr[3*v+2], p0,p1,p2);
            d_pr[i] = make_float4(p0, p1, p2, br[v]);
            norm2 += d_wr[i] * (p0*p0 + p1*p1 + p2*p2);
        }
    }
    // block-reduce norm2 (blocks 2 and 3 only), single writer per slot
    norm2 = warp_sum(norm2);
    if (lane == 0) fpart[wid] = norm2;
    __syncthreads();
    if (wid == 0) {
        float v = fpart[lane];
        v = warp_sum(v);
        if (lane == 0) d_acc[which + 1] = (double)v;   // which 2 -> acc[3], 3 -> acc[4]
    }
}

// ---------------- loss kernel: dynamic tile ticketing + in-kernel finalize -------
__global__ void __launch_bounds__(256)
loss_kernel(const float* __restrict__ G, const float* __restrict__ R,
            const float* __restrict__ A, float* __restrict__ out) {
    __shared__ float4 sq[64];
    __shared__ int    soff[64];
    __shared__ float  sw[64];
    __shared__ float  red[8];
    __shared__ int    s_tile;
    const int tid = threadIdx.x, lane = tid & 31, wid = tid >> 5;

    const int nu1 = d_nu[0], nu2 = d_nu[1], nug = d_nu[2], nur = d_nu[3];
    const int gxr = (nur + 255) / 256;                  // j-blocks over mr axis
    const int nb3 = gxr * ((nug + 63) / 64);
    const int nb2 = gxr * ((nu2 + 63) / 64);
    const int gx1 = (nug + 255) / 256;
    const int nb1 = gx1 * ((nu1 + 31) / 32);
    const int nbt = nb3 + nb2 + nb1;

    for (;;) {
        if (tid == 0) s_tile = atomicAdd(&d_ticket, 1);
        __syncthreads();
        int t = s_tile;
        if (t >= nbt) break;

        float part = 0.0f;   // this thread's contribution
        int accIdx;

        if (t < nb3) {
            // ---- loss3: S += w_i w_j * (pg_i . pr_j) * A[sg_i, sr_j] ----
            accIdx = 2;
            const int bx = t % gxr, by = t / gxr;
            const int i0 = by * 64;
            if (tid < 64) {
                int i = i0 + tid;
                if (i < nug) {
                    float4 p = d_pg[i]; float w = d_wg[i];
                    sq[tid] = make_float4(p.x * w, p.y * w, p.z * w, 0.0f);
                    soff[tid] = d_sg[i] * RD;
                }
            }
            __syncthreads();
            const int j = bx * 256 + tid;
            if (j < nur) {
                float4 pj = d_pr[j]; int col = d_sr[j]; float wj = d_wr[j];
                float a0 = 0.0f, a1 = 0.0f, a2 = 0.0f;
                const int ilim = min(64, nug - i0);
                #pragma unroll 4
                for (int i = 0; i < ilim; i++) {
                    float a  = __ldg(A + soff[i] + col);
                    float4 g = sq[i];
                    a0 = fmaf(a, g.x, a0);
                    a1 = fmaf(a, g.y, a1);
                    a2 = fmaf(a, g.z, a2);
                }
                part = (a0 * pj.x + a1 * pj.y + a2 * pj.z) * wj;
            }
        } else {
            // ---- weighted squared-residual losses ----
            const float* X; int ld, TI, bx, by, nu_i, nu_j;
            const int *si, *sj; const float *wiA, *wjA; const float4 *qA, *pA;
            int u = t - nb3;
            if (u < nb2) {          // loss2 over R
                X = R; ld = RD; TI = 64; bx = u % gxr; by = u / gxr;
                nu_i = nu2; nu_j = nur; accIdx = 1;
                si = d_s2; wiA = d_w2; qA = d_q2; sj = d_sr; wjA = d_wr; pA = d_pr;
            } else {                // loss1 over G
                u -= nb2;
                X = G; ld = GD; TI = 32; bx = u % gx1; by = u / gx1;
                nu_i = nu1; nu_j = nug; accIdx = 0;
                si = d_s1; wiA = d_w1; qA = d_q1; sj = d_sg; wjA = d_wg; pA = d_pg;
            }
            const int i0 = by * TI;
            if (tid < TI) {
                int i = i0 + tid;
                if (i < nu_i) { sq[tid] = qA[i]; soff[tid] = si[i] * ld; sw[tid] = wiA[i]; }
            }
            __syncthreads();
            const int j = bx * 256 + tid;
            if (j < nu_j) {
                float4 pj = pA[j]; int col = sj[j]; float wj = wjA[j];
                float acc = 0.0f;
                const int ilim = min(TI, nu_i - i0);
                #pragma unroll 4
                for (int i = 0; i < ilim; i++) {
                    float4 qi = sq[i];
                    float g = __ldg(X + soff[i] + col);
                    float r = g - fmaf(qi.x, pj.x, fmaf(qi.y, pj.y, qi.z * pj.z))
                                - pj.w - qi.w;
                    acc = fmaf(sw[i] * r, r, acc);
                }
                part = acc * wj;
            }
        }

        // warp-shuffle block reduction -> one double atomic per tile
        part = warp_sum(part);
        if (lane == 0) red[wid] = part;
        __syncthreads();
        if (wid == 0) {
            float v = (lane < 8) ? red[lane] : 0.0f;
            #pragma unroll
            for (int off = 4; off > 0; off >>= 1)
                v += __shfl_down_sync(0xFFFFFFFFu, v, off);
            if (lane == 0) atomicAdd(&d_acc[accIdx], (double)v);
        }
        __syncthreads();   // smem reuse guard for next tile
    }

    // ---- completion: last block finalizes ----
    __threadfence();
    __syncthreads();
    if (tid == 0) {
        int prev = atomicAdd(&d_done, 1);
        if (prev == (int)gridDim.x - 1) {
            // atomic reads bypass L1 -> guaranteed fresh after the fence protocol
            double a0 = atomicAdd(&d_acc[0], 0.0);
            double a1 = atomicAdd(&d_acc[1], 0.0);
            double a2 = atomicAdd(&d_acc[2], 0.0);
            double a3 = atomicAdd(&d_acc[3], 0.0);
            double a4 = atomicAdd(&d_acc[4], 0.0);
            double t1 = 1000.0 * (a0 / (double)((long long)M1v * MGv));
            double t2 = 1000.0 * (a1 / (double)((long long)M2v * MRv));
            double t3 = 100.0  * (-a2 / (sqrt(a3) * sqrt(a4)));
            out[0] = (float)(t1 + t2 + t3);
            out[1] = (float)t1;
            out[2] = (float)t2;
            out[3] = (float)t3;
            out[4] = 0.0f;   // ALPHA[3] == 0 -> exactly 0
        }
    }
}

// ---------------- launch ----------------
extern "C" void kernel_launch(void* const* d_in, const int* in_sizes, int n_in,
                              void* d_out, int out_size) {
    const float* G  = (const float*)d_in[0];
    const float* R  = (const float*)d_in[1];
    const float* A  = (const float*)d_in[2];
    const float* C1 = (const float*)d_in[3];
    const float* C2 = (const float*)d_in[4];
    const float* Cg = (const float*)d_in[5];
    const float* Cr = (const float*)d_in[6];
    const float* Ai = (const float*)d_in[7];
    const float* bg = (const float*)d_in[8];
    const float* br = (const float*)d_in[9];
    const float* b1 = (const float*)d_in[10];
    const float* b2 = (const float*)d_in[11];
    const int* m1 = (const int*)d_in[12];
    const int* m2 = (const int*)d_in[13];
    const int* mg = (const int*)d_in[14];
    const int* mr = (const int*)d_in[15];
    float* out = (float*)d_out;

    // largest histogram (R_DIM = 20000 ints = 80 KB) exceeds default 48 KB
    cudaFuncSetAttribute(sort_prep_kernel,
                         cudaFuncAttributeMaxDynamicSharedMemorySize,
                         RD * (int)sizeof(int));

    sort_prep_kernel<<<4, 1024, RD * sizeof(int)>>>(m1, m2, mg, mr,
                                                    C1, C2, Cg, Cr, Ai,
                                                    bg, br, b1, b2);
    loss_kernel<<<NBLK, 256>>>(G, R, A, out);
}